// round 1
// baseline (speedup 1.0000x reference)
#include <cuda_runtime.h>

// ROIAlign / crop_and_resize (bilinear, extrapolation_value = 0)
// feature_map: [8, 64, 64, 256] f32   (B,H,W,C), C contiguous
// rois:        [8, 128, 4]      f32   normalized [y1,x1,y2,x2]
// out:         [1024, 14, 14, 256] f32
//
// One "pixel task" = (roi n, out row i, out col j). 64 lanes cover the 256
// channels with float4 loads/stores (fully coalesced, 16B aligned).
// 256-thread blocks process 4 pixel tasks each.

#define B 8
#define H 64
#define W 64
#define C 256
#define NUM_ROIS 128
#define N_TOTAL (B * NUM_ROIS)      // 1024
#define CROP 14
#define PIX_PER_ROI (CROP * CROP)   // 196
#define TOTAL_PIX (N_TOTAL * PIX_PER_ROI)  // 200704
#define PIX_PER_BLOCK 4

__global__ __launch_bounds__(256) void roialign_kernel(
    const float* __restrict__ fm,
    const float* __restrict__ rois,
    float* __restrict__ out)
{
    const int lane = threadIdx.x & 63;        // 0..63 : channel group
    const int sub  = threadIdx.x >> 6;        // 0..3  : pixel within block
    const int pix  = blockIdx.x * PIX_PER_BLOCK + sub;
    if (pix >= TOTAL_PIX) return;

    // Decompose pixel id
    const int n   = pix / PIX_PER_ROI;        // roi index 0..1023
    const int rem = pix - n * PIX_PER_ROI;
    const int i   = rem / CROP;               // out row
    const int j   = rem - i * CROP;           // out col
    const int b   = n >> 7;                   // n / 128  (batch)

    // ROI coords (broadcast load across the 64 lanes — L1 hit)
    const float4 r = __ldg((const float4*)(rois + n * 4));
    const float y1 = r.x, x1 = r.y, y2 = r.z, x2 = r.w;

    const float h_scale = (y2 - y1) * (float)(H - 1) / (float)(CROP - 1);
    const float w_scale = (x2 - x1) * (float)(W - 1) / (float)(CROP - 1);
    const float in_y = fmaf((float)i, h_scale, y1 * (float)(H - 1));
    const float in_x = fmaf((float)j, w_scale, x1 * (float)(W - 1));

    float* op = out + ((size_t)pix * C) + lane * 4;

    const bool valid = (in_y >= 0.f) && (in_y <= (float)(H - 1)) &&
                       (in_x >= 0.f) && (in_x <= (float)(W - 1));
    if (!valid) {
        *(float4*)op = make_float4(0.f, 0.f, 0.f, 0.f);
        return;
    }

    const float fy = floorf(in_y);
    const float fx = floorf(in_x);
    const float y_lerp = in_y - fy;
    const float x_lerp = in_x - fx;

    int ty = (int)fy;            // valid => fy in [0, 63]
    int by = (int)ceilf(in_y);
    int lx = (int)fx;
    int rx = (int)ceilf(in_x);
    // clips (ceil can be 64 only if in_y == 63 exactly? no: in_y<=63 => ceil<=63;
    // keep clips for safety against fp edge cases)
    if (ty < 0) ty = 0; if (ty > H - 1) ty = H - 1;
    if (by < 0) by = 0; if (by > H - 1) by = H - 1;
    if (lx < 0) lx = 0; if (lx > W - 1) lx = W - 1;
    if (rx < 0) rx = 0; if (rx > W - 1) rx = W - 1;

    const size_t base = (size_t)b * H * W * C;
    const int c4 = lane * 4;
    const float4 tl = __ldg((const float4*)(fm + base + ((size_t)(ty * W + lx)) * C + c4));
    const float4 tr = __ldg((const float4*)(fm + base + ((size_t)(ty * W + rx)) * C + c4));
    const float4 bl = __ldg((const float4*)(fm + base + ((size_t)(by * W + lx)) * C + c4));
    const float4 br = __ldg((const float4*)(fm + base + ((size_t)(by * W + rx)) * C + c4));

    float4 o;
    {
        float top, bot;
        top = fmaf(tr.x - tl.x, x_lerp, tl.x);
        bot = fmaf(br.x - bl.x, x_lerp, bl.x);
        o.x = fmaf(bot - top, y_lerp, top);
        top = fmaf(tr.y - tl.y, x_lerp, tl.y);
        bot = fmaf(br.y - bl.y, x_lerp, bl.y);
        o.y = fmaf(bot - top, y_lerp, top);
        top = fmaf(tr.z - tl.z, x_lerp, tl.z);
        bot = fmaf(br.z - bl.z, x_lerp, bl.z);
        o.z = fmaf(bot - top, y_lerp, top);
        top = fmaf(tr.w - tl.w, x_lerp, tl.w);
        bot = fmaf(br.w - bl.w, x_lerp, bl.w);
        o.w = fmaf(bot - top, y_lerp, top);
    }
    *(float4*)op = o;
}

extern "C" void kernel_launch(void* const* d_in, const int* in_sizes, int n_in,
                              void* d_out, int out_size)
{
    const float* fm   = (const float*)d_in[0];
    const float* rois = (const float*)d_in[1];
    float* out = (float*)d_out;

    const int grid = TOTAL_PIX / PIX_PER_BLOCK;   // 50176
    roialign_kernel<<<grid, 256>>>(fm, rois, out);
}